// round 3
// baseline (speedup 1.0000x reference)
#include <cuda_runtime.h>
#include <math.h>

#define BATCH 2
#define NN    256
#define CC    64
#define OO    64
#define GK    8
#define CIN2  128   // C + O for update layer
#define SPB   4     // samples per block for msg/update kernels

// ---------------- device scratch (no allocs allowed) ----------------
__device__ float  g_xT[BATCH * CC * NN];          // x transposed: [b][c][n]
__device__ float  g_alpha[BATCH * NN * NN];       // softmax attention
__device__ float  g_msg[BATCH * NN * OO];         // message values
__device__ float4 g_fpoly[CC * 11];               // per-channel per-interval cubic coeffs (energy spline)
__device__ float  g_mswP[CC * OO * GK];           // mw_spline*scaler, layout [c][o][g]
__device__ float  g_mbT [CC * OO];                // mw_base transposed [c][o]
__device__ float  g_uswP[CIN2 * OO * GK];         // uw_spline*scaler, layout [c][o][g]
__device__ float  g_ubT [CIN2 * OO];              // uw_base transposed [c][o]

// Uniform cubic B-spline pieces on local coord u in [0,1):
//   basis index m = j-3+t  (j = knot interval), values:
//   t=0: (1-u)^3/6   t=1: (3u^3-6u^2+4)/6   t=2: (-3u^3+3u^2+3u+1)/6   t=3: u^3/6
__device__ __forceinline__ void basis8(float v, float* pb8, float& sil) {
#pragma unroll
    for (int g = 0; g < GK; g++) pb8[g] = 0.f;
    sil = v * __frcp_rn(1.f + __expf(-v));
    float s  = (v + 2.2f) * 2.5f;       // (v - g0)/h,  g0=-2.2, h=0.4
    float fj = floorf(s);
    int   ji = (int)fj;
    if (ji >= 0 && ji <= 10) {
        float u  = s - fj;
        float u2 = u * u, u3 = u2 * u;
        float um = 1.f - u;
        float b0 = um * um * um * (1.f / 6.f);
        float b1 = (3.f * u3 - 6.f * u2 + 4.f) * (1.f / 6.f);
        float b2 = (-3.f * u3 + 3.f * u2 + 3.f * u + 1.f) * (1.f / 6.f);
        float b3 = u3 * (1.f / 6.f);
        int m = ji - 3;
        if (m     >= 0 && m     < GK) pb8[m]     = b0;
        if (m + 1 >= 0 && m + 1 < GK) pb8[m + 1] = b1;
        if (m + 2 >= 0 && m + 2 < GK) pb8[m + 2] = b2;
        if (m + 3 >= 0 && m + 3 < GK) pb8[m + 3] = b3;
    }
}

// ---------------- K1: precompute (weights reshape + fpoly + x transpose) ----------------
__global__ void precompute_kernel(const float* __restrict__ x,
                                  const float* __restrict__ fw_spline,
                                  const float* __restrict__ fw_scaler,
                                  const float* __restrict__ mw_base,
                                  const float* __restrict__ mw_spline,
                                  const float* __restrict__ mw_scaler,
                                  const float* __restrict__ uw_base,
                                  const float* __restrict__ uw_spline,
                                  const float* __restrict__ uw_scaler) {
    int tid = blockIdx.x * blockDim.x + threadIdx.x;
    int stride = gridDim.x * blockDim.x;

    // x transpose: g_xT[b][c][n] = x[b][n][c]
    for (int idx = tid; idx < BATCH * NN * CC; idx += stride) {
        int c = idx & (CC - 1);
        int n = (idx >> 6) & (NN - 1);
        int b = idx >> 14;
        g_xT[(b * CC + c) * NN + n] = x[idx];
    }
    // msg weights
    for (int idx = tid; idx < CC * OO * GK; idx += stride) {
        int g = idx & 7, rest = idx >> 3;
        int o = rest & 63, c = rest >> 6;
        g_mswP[idx] = mw_spline[(o * CC + c) * GK + g] * mw_scaler[o * CC + c];
    }
    for (int idx = tid; idx < CC * OO; idx += stride) {
        int o = idx & 63, c = idx >> 6;
        g_mbT[idx] = mw_base[o * CC + c];
    }
    // update weights
    for (int idx = tid; idx < CIN2 * OO * GK; idx += stride) {
        int g = idx & 7, rest = idx >> 3;
        int o = rest & 63, c = rest >> 6;
        g_uswP[idx] = uw_spline[(o * CIN2 + c) * GK + g] * uw_scaler[o * CIN2 + c];
    }
    for (int idx = tid; idx < CIN2 * OO; idx += stride) {
        int o = idx & 63, c = idx >> 6;
        g_ubT[idx] = uw_base[o * CIN2 + c];
    }
    // energy spline -> piecewise cubic coeffs per (channel, interval)
    for (int idx = tid; idx < CC * 11; idx += stride) {
        int c = idx / 11, j = idx % 11;
        const float P[4][4] = { {1.f, -3.f, 3.f, -1.f},
                                {4.f,  0.f, -6.f, 3.f},
                                {1.f,  3.f, 3.f, -3.f},
                                {0.f,  0.f, 0.f,  1.f} };
        float a0 = 0.f, a1 = 0.f, a2 = 0.f, a3 = 0.f;
#pragma unroll
        for (int t = 0; t < 4; t++) {
            int m = j - 3 + t;
            if (m >= 0 && m < GK) {
                float w = fw_spline[c * GK + m] * fw_scaler[c] * (1.f / 6.f);
                a0 += w * P[t][0]; a1 += w * P[t][1];
                a2 += w * P[t][2]; a3 += w * P[t][3];
            }
        }
        g_fpoly[idx] = make_float4(a0, a1, a2, a3);
    }
}

// ---------------- K2: msg = kan_linear(x, mw_*) ----------------
__global__ void msg_kernel(const float* __restrict__ x) {
    int s0 = blockIdx.x * SPB;      // global sample index (b*N + n)
    int o  = threadIdx.x;           // 0..63
    __shared__ float pb[SPB][CC][GK];
    __shared__ float sv[SPB][CC];

#pragma unroll
    for (int s = 0; s < SPB; s++) {
        float v = x[(s0 + s) * CC + o];
        float sl;
        basis8(v, &pb[s][o][0], sl);
        sv[s][o] = sl;
    }
    __syncthreads();

    float acc[SPB] = {0.f, 0.f, 0.f, 0.f};
    for (int c = 0; c < CC; c++) {
        float wb = g_mbT[c * OO + o];
        const float4* wp = (const float4*)(g_mswP + (c * OO + o) * GK);
        float4 w0 = wp[0], w1 = wp[1];
#pragma unroll
        for (int s = 0; s < SPB; s++) {
            float a = acc[s];
            a = fmaf(sv[s][c], wb, a);
            a = fmaf(pb[s][c][0], w0.x, a);
            a = fmaf(pb[s][c][1], w0.y, a);
            a = fmaf(pb[s][c][2], w0.z, a);
            a = fmaf(pb[s][c][3], w0.w, a);
            a = fmaf(pb[s][c][4], w1.x, a);
            a = fmaf(pb[s][c][5], w1.y, a);
            a = fmaf(pb[s][c][6], w1.z, a);
            a = fmaf(pb[s][c][7], w1.w, a);
            acc[s] = a;
        }
    }
#pragma unroll
    for (int s = 0; s < SPB; s++) g_msg[(s0 + s) * OO + o] = acc[s];
}

// ---------------- K3: fused energy + mask + softmax ----------------
__global__ void energy_softmax_kernel(const float* __restrict__ x,
                                      const int*   __restrict__ adj,
                                      const float* __restrict__ fw_base) {
    int b = blockIdx.x >> 8;
    int i = blockIdx.x & 255;
    int t = threadIdx.x;            // j index, 0..255

    __shared__ float4 spoly[CC * 11];   // 11264 B
    __shared__ float  sfb[CC];
    __shared__ float  sxi[CC];
    __shared__ float  red[NN];

    for (int idx = t; idx < CC * 11; idx += NN) spoly[idx] = g_fpoly[idx];
    if (t < CC) {
        sfb[t] = fw_base[t];
        sxi[t] = x[(b * NN + i) * CC + t];
    }
    __syncthreads();

    const float* xb = g_xT + b * CC * NN;
    float e = 0.f;
#pragma unroll 4
    for (int c = 0; c < CC; c++) {
        float r = sxi[c] - xb[c * NN + t];
        // SiLU base branch
        e = fmaf(sfb[c] * r, __frcp_rn(1.f + __expf(-r)), e);
        // spline branch via per-interval cubic
        float s  = (r + 2.2f) * 2.5f;
        float fj = floorf(s);
        int   ji = (int)fj;
        if (ji >= 0 && ji <= 10) {
            float u = s - fj;
            float4 a = spoly[c * 11 + ji];
            e += fmaf(fmaf(fmaf(a.w, u, a.z), u, a.y), u, a.x);
        }
    }
    if (adj[(b * NN + i) * NN + t] == 0) e = -1e9f;

    // softmax over j
    red[t] = e;
    __syncthreads();
    for (int sft = NN / 2; sft > 0; sft >>= 1) {
        if (t < sft) red[t] = fmaxf(red[t], red[t + sft]);
        __syncthreads();
    }
    float m = red[0];
    __syncthreads();
    float ev = __expf(e - m);
    red[t] = ev;
    __syncthreads();
    for (int sft = NN / 2; sft > 0; sft >>= 1) {
        if (t < sft) red[t] += red[t + sft];
        __syncthreads();
    }
    float inv = __frcp_rn(red[0]);
    g_alpha[(b * NN + i) * NN + t] = ev * inv;
}

// ---------------- K4: aggr = alpha @ msg ; out = kan_linear([x, aggr], uw_*) ----------------
__global__ void update_kernel(const float* __restrict__ x,
                              float* __restrict__ out) {
    int s0 = blockIdx.x * SPB;      // SPB=4 divides 256 -> same b within block
    int o  = threadIdx.x;           // 0..63
    int b  = s0 >> 8;

    __shared__ float sal[SPB][NN];
    __shared__ float pb[SPB][CIN2][GK];
    __shared__ float sv[SPB][CIN2];

    for (int idx = o; idx < SPB * NN; idx += OO) {
        int s = idx >> 8;
        int j = idx & 255;
        sal[s][j] = g_alpha[(s0 + s) * NN + j];
    }
    __syncthreads();

    const float* mbatch = g_msg + b * NN * OO;
    float aggr[SPB];
#pragma unroll
    for (int s = 0; s < SPB; s++) {
        float a = 0.f;
#pragma unroll 4
        for (int j = 0; j < NN; j++) a = fmaf(sal[s][j], mbatch[j * OO + o], a);
        aggr[s] = a;
    }
#pragma unroll
    for (int s = 0; s < SPB; s++) {
        float v0 = x[(s0 + s) * CC + o];
        float sl;
        basis8(v0, &pb[s][o][0], sl);
        sv[s][o] = sl;
        basis8(aggr[s], &pb[s][CC + o][0], sl);
        sv[s][CC + o] = sl;
    }
    __syncthreads();

    float acc[SPB] = {0.f, 0.f, 0.f, 0.f};
    for (int c = 0; c < CIN2; c++) {
        float wb = g_ubT[c * OO + o];
        const float4* wp = (const float4*)(g_uswP + (c * OO + o) * GK);
        float4 w0 = wp[0], w1 = wp[1];
#pragma unroll
        for (int s = 0; s < SPB; s++) {
            float a = acc[s];
            a = fmaf(sv[s][c], wb, a);
            a = fmaf(pb[s][c][0], w0.x, a);
            a = fmaf(pb[s][c][1], w0.y, a);
            a = fmaf(pb[s][c][2], w0.z, a);
            a = fmaf(pb[s][c][3], w0.w, a);
            a = fmaf(pb[s][c][4], w1.x, a);
            a = fmaf(pb[s][c][5], w1.y, a);
            a = fmaf(pb[s][c][6], w1.z, a);
            a = fmaf(pb[s][c][7], w1.w, a);
            acc[s] = a;
        }
    }
#pragma unroll
    for (int s = 0; s < SPB; s++) out[(s0 + s) * OO + o] = acc[s];
}

// ---------------- launch ----------------
extern "C" void kernel_launch(void* const* d_in, const int* in_sizes, int n_in,
                              void* d_out, int out_size) {
    const float* x         = (const float*)d_in[0];
    const int*   adj       = (const int*)  d_in[1];
    const float* fw_base   = (const float*)d_in[2];
    const float* fw_spline = (const float*)d_in[3];
    const float* fw_scaler = (const float*)d_in[4];
    const float* mw_base   = (const float*)d_in[5];
    const float* mw_spline = (const float*)d_in[6];
    const float* mw_scaler = (const float*)d_in[7];
    const float* uw_base   = (const float*)d_in[8];
    const float* uw_spline = (const float*)d_in[9];
    const float* uw_scaler = (const float*)d_in[10];
    float* out = (float*)d_out;

    precompute_kernel<<<64, 256>>>(x, fw_spline, fw_scaler,
                                   mw_base, mw_spline, mw_scaler,
                                   uw_base, uw_spline, uw_scaler);
    msg_kernel<<<(BATCH * NN) / SPB, OO>>>(x);
    energy_softmax_kernel<<<BATCH * NN, NN>>>(x, adj, fw_base);
    update_kernel<<<(BATCH * NN) / SPB, OO>>>(x, out);
}

// round 4
// speedup vs baseline: 1.9613x; 1.9613x over previous
#include <cuda_runtime.h>
#include <math.h>

#define BATCH 2
#define NN    256
#define CC    64
#define OO    64
#define GK    8
#define CIN2  128   // C + O for update layer
#define SPB   4     // samples per block for msg/update kernels

// ---------------- device scratch (no allocs allowed) ----------------
__device__ float  g_xT[BATCH * CC * NN];     // x transposed: [b][c][n]
__device__ float  g_alpha[BATCH * NN * NN];  // softmax attention
__device__ float  g_msg[BATCH * NN * OO];    // message values [sample][o]
__device__ float4 g_fpoly[CC * 11];          // per-(channel,interval) cubic coeffs (energy spline)
__device__ float  g_mw9[CC * 9 * OO];        // msg weights [c][k][o], k=0 base, k=1..8 spline*scaler
__device__ float  g_uw9[CIN2 * 9 * OO];      // update weights [c][k][o]

// Uniform cubic B-spline: writes 8 basis values to p[k*SPB], k=0..7, plus SiLU.
__device__ __forceinline__ void basis8_s(float v, float* p, float& sil) {
#pragma unroll
    for (int g = 0; g < GK; g++) p[g * SPB] = 0.f;
    sil = v * __frcp_rn(1.f + __expf(-v));
    float s  = (v + 2.2f) * 2.5f;       // (v - g0)/h,  g0=-2.2, h=0.4
    float fj = floorf(s);
    int   ji = (int)fj;
    if (ji >= 0 && ji <= 10) {
        float u  = s - fj;
        float u2 = u * u, u3 = u2 * u;
        float um = 1.f - u;
        float b0 = um * um * um * (1.f / 6.f);
        float b1 = (3.f * u3 - 6.f * u2 + 4.f) * (1.f / 6.f);
        float b2 = (-3.f * u3 + 3.f * u2 + 3.f * u + 1.f) * (1.f / 6.f);
        float b3 = u3 * (1.f / 6.f);
        int m = ji - 3;
        if (m     >= 0 && m     < GK) p[ m      * SPB] = b0;
        if (m + 1 >= 0 && m + 1 < GK) p[(m + 1) * SPB] = b1;
        if (m + 2 >= 0 && m + 2 < GK) p[(m + 2) * SPB] = b2;
        if (m + 3 >= 0 && m + 3 < GK) p[(m + 3) * SPB] = b3;
    }
}

// ---------------- K1: precompute (weight relayout + fpoly + x transpose) ----------------
__global__ void precompute_kernel(const float* __restrict__ x,
                                  const float* __restrict__ fw_spline,
                                  const float* __restrict__ fw_scaler,
                                  const float* __restrict__ mw_base,
                                  const float* __restrict__ mw_spline,
                                  const float* __restrict__ mw_scaler,
                                  const float* __restrict__ uw_base,
                                  const float* __restrict__ uw_spline,
                                  const float* __restrict__ uw_scaler) {
    int tid = blockIdx.x * blockDim.x + threadIdx.x;
    int stride = gridDim.x * blockDim.x;

    // x transpose: g_xT[b][c][n] = x[b][n][c]
    for (int idx = tid; idx < BATCH * NN * CC; idx += stride) {
        int c = idx & (CC - 1);
        int n = (idx >> 6) & (NN - 1);
        int b = idx >> 14;
        g_xT[(b * CC + c) * NN + n] = x[idx];
    }
    // msg weights: [c][k][o]
    for (int idx = tid; idx < CC * 9 * OO; idx += stride) {
        int o = idx & 63;
        int k = (idx >> 6) % 9;
        int c = idx / (9 * OO);
        float w;
        if (k == 0) w = mw_base[o * CC + c];
        else        w = mw_spline[(o * CC + c) * GK + (k - 1)] * mw_scaler[o * CC + c];
        g_mw9[idx] = w;
    }
    // update weights: [c][k][o]
    for (int idx = tid; idx < CIN2 * 9 * OO; idx += stride) {
        int o = idx & 63;
        int k = (idx >> 6) % 9;
        int c = idx / (9 * OO);
        float w;
        if (k == 0) w = uw_base[o * CIN2 + c];
        else        w = uw_spline[(o * CIN2 + c) * GK + (k - 1)] * uw_scaler[o * CIN2 + c];
        g_uw9[idx] = w;
    }
    // energy spline -> piecewise cubic coeffs per (channel, interval)
    for (int idx = tid; idx < CC * 11; idx += stride) {
        int c = idx / 11, j = idx % 11;
        const float P[4][4] = { {1.f, -3.f, 3.f, -1.f},
                                {4.f,  0.f, -6.f, 3.f},
                                {1.f,  3.f, 3.f, -3.f},
                                {0.f,  0.f, 0.f,  1.f} };
        float a0 = 0.f, a1 = 0.f, a2 = 0.f, a3 = 0.f;
#pragma unroll
        for (int t = 0; t < 4; t++) {
            int m = j - 3 + t;
            if (m >= 0 && m < GK) {
                float w = fw_spline[c * GK + m] * fw_scaler[c] * (1.f / 6.f);
                a0 += w * P[t][0]; a1 += w * P[t][1];
                a2 += w * P[t][2]; a3 += w * P[t][3];
            }
        }
        g_fpoly[idx] = make_float4(a0, a1, a2, a3);
    }
}

// ---------------- K2: msg = kan_linear(x, mw_*)  (256 thr, SPB=4 samples) ----------------
__global__ __launch_bounds__(256) void msg_kernel(const float* __restrict__ x) {
    int s0 = blockIdx.x * SPB;
    int t  = threadIdx.x;
    __shared__ float sval[CC * 9 * SPB];      // [c][k][s], 9216 B
    __shared__ float part[4][SPB][OO];        // 4096 B

    int s = t >> 6, c = t & 63;
    {
        float v = x[(s0 + s) * CC + c];
        float sil;
        basis8_s(v, &sval[(c * 9 + 1) * SPB + s], sil);
        sval[(c * 9) * SPB + s] = sil;
    }
    __syncthreads();

    int o = t & 63, q = t >> 6;
    float4 acc = make_float4(0.f, 0.f, 0.f, 0.f);
    const float* wb = g_mw9 + o;
#pragma unroll 9
    for (int ck = q * 16 * 9; ck < (q * 16 + 16) * 9; ck++) {
        float  w  = wb[ck * OO];
        float4 vv = *(const float4*)&sval[ck * SPB];
        acc.x = fmaf(vv.x, w, acc.x);
        acc.y = fmaf(vv.y, w, acc.y);
        acc.z = fmaf(vv.z, w, acc.z);
        acc.w = fmaf(vv.w, w, acc.w);
    }
    part[q][0][o] = acc.x; part[q][1][o] = acc.y;
    part[q][2][o] = acc.z; part[q][3][o] = acc.w;
    __syncthreads();
    {
        float r = part[0][s][c] + part[1][s][c] + part[2][s][c] + part[3][s][c];
        g_msg[(s0 + s) * OO + c] = r;
    }
}

// ---------------- K3: fused energy + mask + softmax ----------------
__global__ __launch_bounds__(256) void energy_softmax_kernel(const float* __restrict__ x,
                                                             const int*   __restrict__ adj,
                                                             const float* __restrict__ fw_base) {
    int b = blockIdx.x >> 8;
    int i = blockIdx.x & 255;
    int t = threadIdx.x;            // j index, 0..255

    __shared__ float4 spoly[CC * 11];   // 11264 B
    __shared__ float  sfb[CC];
    __shared__ float  sxi[CC];
    __shared__ float  wred[8];

    for (int idx = t; idx < CC * 11; idx += NN) spoly[idx] = g_fpoly[idx];
    if (t < CC) {
        sfb[t] = fw_base[t];
        sxi[t] = x[(b * NN + i) * CC + t];
    }
    __syncthreads();

    const float* xb = g_xT + b * CC * NN;
    float e = 0.f;
#pragma unroll 4
    for (int c = 0; c < CC; c++) {
        float r = sxi[c] - xb[c * NN + t];
        e = fmaf(sfb[c] * r, __frcp_rn(1.f + __expf(-r)), e);
        float s  = (r + 2.2f) * 2.5f;
        float fj = floorf(s);
        int   ji = (int)fj;
        if (ji >= 0 && ji <= 10) {
            float u = s - fj;
            float4 a = spoly[c * 11 + ji];
            e += fmaf(fmaf(fmaf(a.w, u, a.z), u, a.y), u, a.x);
        }
    }
    if (adj[(b * NN + i) * NN + t] == 0) e = -1e9f;

    // softmax over j: warp shuffles + 8-entry shared
    int lane = t & 31, w = t >> 5;
    float m = e;
#pragma unroll
    for (int ofs = 16; ofs; ofs >>= 1)
        m = fmaxf(m, __shfl_xor_sync(0xffffffffu, m, ofs));
    if (lane == 0) wred[w] = m;
    __syncthreads();
    float mm = wred[0];
#pragma unroll
    for (int k = 1; k < 8; k++) mm = fmaxf(mm, wred[k]);

    float ev = __expf(e - mm);
    float sum = ev;
#pragma unroll
    for (int ofs = 16; ofs; ofs >>= 1)
        sum += __shfl_xor_sync(0xffffffffu, sum, ofs);
    __syncthreads();
    if (lane == 0) wred[w] = sum;
    __syncthreads();
    float tot = wred[0];
#pragma unroll
    for (int k = 1; k < 8; k++) tot += wred[k];

    g_alpha[(b * NN + i) * NN + t] = ev * __frcp_rn(tot);
}

// ---------------- K4: aggr = alpha @ msg ; out = kan_linear([x, aggr], uw_*) ----------------
__global__ __launch_bounds__(256) void update_kernel(const float* __restrict__ x,
                                                     float* __restrict__ out) {
    int s0 = blockIdx.x * SPB;      // SPB=4 divides 256 -> same b within block
    int b  = s0 >> 8;
    int t  = threadIdx.x;

    __shared__ float salT[NN * SPB];          // alpha transposed [j][s], 4096 B
    __shared__ float sval[CIN2 * 9 * SPB];    // [c][k][s], 18432 B
    __shared__ float part[4][SPB][OO];        // 4096 B
    __shared__ float aggr_s[SPB][OO];         // 1024 B

    for (int idx = t; idx < SPB * NN; idx += 256) {
        int j = idx & 255, s = idx >> 8;
        salT[j * SPB + s] = g_alpha[(s0 + s) * NN + j];
    }
    __syncthreads();

    int o = t & 63, q = t >> 6;
    // aggr: each thread sums its quarter of j for all 4 samples
    {
        const float* mb = g_msg + b * NN * OO + o;
        float4 acc = make_float4(0.f, 0.f, 0.f, 0.f);
#pragma unroll 8
        for (int j = q * 64; j < q * 64 + 64; j++) {
            float  w  = mb[j * OO];
            float4 a4 = *(const float4*)&salT[j * SPB];
            acc.x = fmaf(a4.x, w, acc.x);
            acc.y = fmaf(a4.y, w, acc.y);
            acc.z = fmaf(a4.z, w, acc.z);
            acc.w = fmaf(a4.w, w, acc.w);
        }
        part[q][0][o] = acc.x; part[q][1][o] = acc.y;
        part[q][2][o] = acc.z; part[q][3][o] = acc.w;
    }
    __syncthreads();

    int s = t >> 6, c = t & 63;
    {
        float a = part[0][s][c] + part[1][s][c] + part[2][s][c] + part[3][s][c];
        aggr_s[s][c] = a;
    }
    // basis for 128 channels: this thread does (s, c) and (s, c+64)
    {
        float sil;
        float v0 = x[(s0 + s) * CC + c];
        basis8_s(v0, &sval[(c * 9 + 1) * SPB + s], sil);
        sval[(c * 9) * SPB + s] = sil;
        float v1 = aggr_s[s][c];
        basis8_s(v1, &sval[((c + 64) * 9 + 1) * SPB + s], sil);
        sval[((c + 64) * 9) * SPB + s] = sil;
    }
    __syncthreads();

    float4 acc = make_float4(0.f, 0.f, 0.f, 0.f);
    const float* wb = g_uw9 + o;
#pragma unroll 9
    for (int ck = q * 32 * 9; ck < (q * 32 + 32) * 9; ck++) {
        float  w  = wb[ck * OO];
        float4 vv = *(const float4*)&sval[ck * SPB];
        acc.x = fmaf(vv.x, w, acc.x);
        acc.y = fmaf(vv.y, w, acc.y);
        acc.z = fmaf(vv.z, w, acc.z);
        acc.w = fmaf(vv.w, w, acc.w);
    }
    part[q][0][o] = acc.x; part[q][1][o] = acc.y;
    part[q][2][o] = acc.z; part[q][3][o] = acc.w;
    __syncthreads();
    {
        float r = part[0][s][c] + part[1][s][c] + part[2][s][c] + part[3][s][c];
        out[(s0 + s) * OO + c] = r;
    }
}

// ---------------- launch ----------------
extern "C" void kernel_launch(void* const* d_in, const int* in_sizes, int n_in,
                              void* d_out, int out_size) {
    const float* x         = (const float*)d_in[0];
    const int*   adj       = (const int*)  d_in[1];
    const float* fw_base   = (const float*)d_in[2];
    const float* fw_spline = (const float*)d_in[3];
    const float* fw_scaler = (const float*)d_in[4];
    const float* mw_base   = (const float*)d_in[5];
    const float* mw_spline = (const float*)d_in[6];
    const float* mw_scaler = (const float*)d_in[7];
    const float* uw_base   = (const float*)d_in[8];
    const float* uw_spline = (const float*)d_in[9];
    const float* uw_scaler = (const float*)d_in[10];
    float* out = (float*)d_out;

    precompute_kernel<<<64, 256>>>(x, fw_spline, fw_scaler,
                                   mw_base, mw_spline, mw_scaler,
                                   uw_base, uw_spline, uw_scaler);
    msg_kernel<<<(BATCH * NN) / SPB, 256>>>(x);
    energy_softmax_kernel<<<BATCH * NN, NN>>>(x, adj, fw_base);
    update_kernel<<<(BATCH * NN) / SPB, 256>>>(x, out);
}